// round 14
// baseline (speedup 1.0000x reference)
#include <cuda_runtime.h>
#include <cstdint>
#include <cstddef>

#define NROWS 16384

// Scratch ping-pong buffers (allocation-free: __device__ globals).
__device__ float g_h[NROWS * 64];
__device__ float g_p[NROWS * 64];

// ---------------------------------------------------------------------------
// Packed f32x2 helpers (sm_103a FFMA2 — only reachable via PTX)
// ---------------------------------------------------------------------------
__device__ __forceinline__ unsigned long long bcast2(float x) {
    unsigned long long r;
    unsigned xi = __float_as_uint(x);
    asm("mov.b64 %0, {%1, %1};" : "=l"(r) : "r"(xi));
    return r;
}
__device__ __forceinline__ void fma2(unsigned long long& d,
                                     unsigned long long a,
                                     unsigned long long b) {
    asm("fma.rn.f32x2 %0, %1, %2, %0;" : "+l"(d) : "l"(a), "l"(b));
}
__device__ __forceinline__ void cp_async16(uint32_t dst, const void* src) {
    asm volatile("cp.async.cg.shared.global [%0], [%1], 16;" :: "r"(dst), "l"(src));
}
__device__ __forceinline__ void cp_commit() {
    asm volatile("cp.async.commit_group;" ::: "memory");
}
__device__ __forceinline__ void cp_wait_all() {
    asm volatile("cp.async.wait_group 0;" ::: "memory");
}

// ---------------------------------------------------------------------------
// Big aggregation: C[N, D] = A[N, N] @ P[N, D] + bias[D]
//   BM = 128 rows per block, BN = D (full width), BK = 32.
//   256 threads; per-thread tile: 8 rows (4 f32x2 pairs) x TN cols, TN = D/16.
//   A tile in smem transposed [k][m] with stride 130 (8B-aligned pair loads).
//   A is register double-buffered (LDG.128), P double-buffered via cp.async.
// ---------------------------------------------------------------------------
template<int D>
__global__ void __launch_bounds__(256, 1)
gcn_aggregate(const float* __restrict__ A, const float* __restrict__ P,
              const float* __restrict__ bias, float* __restrict__ C)
{
    constexpr int BM = 128;
    constexpr int BK = 32;
    constexpr int SAS = BM + 2;   // 130: 8B-aligned rows, <=2-way STS conflict
    constexpr int TN = D / 16;    // 4 (D=64) or 1 (D=16)
    constexpr int PF4 = BK * D / 4;  // float4 count of P tile

    __shared__ __align__(16) float As[BK * SAS];
    __shared__ __align__(16) float Ps[2][BK * D];

    const int tid = threadIdx.x;
    const int tx  = tid & 15;     // column group (16)
    const int ty  = tid >> 4;     // row group (16) -> rows ty*8 .. ty*8+7
    const int m0  = blockIdx.x * BM;
    const int lm  = tid >> 3;            // loader row base (0..31)
    const int lk4 = (tid & 7) << 2;      // loader k offset (0,4,..,28)

    const uint32_t ps_base0 = (uint32_t)__cvta_generic_to_shared(&Ps[0][0]);
    const uint32_t ps_base1 = (uint32_t)__cvta_generic_to_shared(&Ps[1][0]);

    unsigned long long acc[4][TN];
    #pragma unroll
    for (int mi = 0; mi < 4; mi++)
        #pragma unroll
        for (int n = 0; n < TN; n++)
            acc[mi][n] = 0ull;

    float4 a_reg[4];

    // ---- prologue: tile 0 ----
    for (int i = tid; i < PF4; i += 256) {
        const int k = i / (D / 4);
        const int c = i % (D / 4);
        cp_async16(ps_base0 + (uint32_t)((k * D + c * 4) * 4),
                   P + (size_t)k * D + c * 4);
    }
    cp_commit();

    #pragma unroll
    for (int j = 0; j < 4; j++)
        a_reg[j] = *reinterpret_cast<const float4*>(
            A + (size_t)(m0 + lm + j * 32) * NROWS + lk4);
    #pragma unroll
    for (int j = 0; j < 4; j++) {
        const int m = lm + j * 32;
        As[(lk4 + 0) * SAS + m] = a_reg[j].x;
        As[(lk4 + 1) * SAS + m] = a_reg[j].y;
        As[(lk4 + 2) * SAS + m] = a_reg[j].z;
        As[(lk4 + 3) * SAS + m] = a_reg[j].w;
    }
    cp_wait_all();
    __syncthreads();

    const int KT = NROWS / BK;   // 512
    for (int kt = 0; kt < KT; kt++) {
        const bool more = (kt + 1) < KT;
        const int k0n = (kt + 1) * BK;
        if (more) {
            // prefetch next A tile into registers
            #pragma unroll
            for (int j = 0; j < 4; j++)
                a_reg[j] = *reinterpret_cast<const float4*>(
                    A + (size_t)(m0 + lm + j * 32) * NROWS + k0n + lk4);
            // prefetch next P tile via cp.async into the other buffer
            const uint32_t pb = ((kt + 1) & 1) ? ps_base1 : ps_base0;
            for (int i = tid; i < PF4; i += 256) {
                const int k = i / (D / 4);
                const int c = i % (D / 4);
                cp_async16(pb + (uint32_t)((k * D + c * 4) * 4),
                           P + (size_t)(k0n + k) * D + c * 4);
            }
            cp_commit();
        }

        // ---- compute on current tile ----
        const float* ps = Ps[kt & 1];
        #pragma unroll
        for (int k = 0; k < BK; k++) {
            unsigned long long a2[4];
            #pragma unroll
            for (int mi = 0; mi < 4; mi++)
                a2[mi] = *reinterpret_cast<const unsigned long long*>(
                    &As[k * SAS + ty * 8 + mi * 2]);
            if constexpr (TN == 4) {
                const float4 pv = *reinterpret_cast<const float4*>(&ps[k * D + tx * 4]);
                const unsigned long long pb0 = bcast2(pv.x);
                const unsigned long long pb1 = bcast2(pv.y);
                const unsigned long long pb2 = bcast2(pv.z);
                const unsigned long long pb3 = bcast2(pv.w);
                #pragma unroll
                for (int mi = 0; mi < 4; mi++) {
                    fma2(acc[mi][0], a2[mi], pb0);
                    fma2(acc[mi][1], a2[mi], pb1);
                    fma2(acc[mi][2], a2[mi], pb2);
                    fma2(acc[mi][3], a2[mi], pb3);
                }
            } else {
                const unsigned long long pb0 = bcast2(ps[k * D + tx]);
                #pragma unroll
                for (int mi = 0; mi < 4; mi++)
                    fma2(acc[mi][0], a2[mi], pb0);
            }
        }
        __syncthreads();   // compute done, As free for overwrite

        if (more) {
            #pragma unroll
            for (int j = 0; j < 4; j++) {
                const int m = lm + j * 32;
                As[(lk4 + 0) * SAS + m] = a_reg[j].x;
                As[(lk4 + 1) * SAS + m] = a_reg[j].y;
                As[(lk4 + 2) * SAS + m] = a_reg[j].z;
                As[(lk4 + 3) * SAS + m] = a_reg[j].w;
            }
            cp_wait_all();
        }
        __syncthreads();   // As + Ps[next] ready
    }

    // ---- epilogue: add bias, store ----
    float bv[TN];
    #pragma unroll
    for (int n = 0; n < TN; n++) bv[n] = bias[tx * TN + n];

    #pragma unroll
    for (int mi = 0; mi < 4; mi++) {
        const int row = m0 + ty * 8 + mi * 2;
        #pragma unroll
        for (int n = 0; n < TN; n++) {
            const unsigned long long v = acc[mi][n];
            const float lo = __uint_as_float((unsigned)(v & 0xffffffffull));
            const float hi = __uint_as_float((unsigned)(v >> 32));
            C[(size_t)row * D + tx * TN + n]       = lo + bv[n];
            C[(size_t)(row + 1) * D + tx * TN + n] = hi + bv[n];
        }
    }
}

// ---------------------------------------------------------------------------
// Small dense GEMM: P[N, DOUT] = H[N, DIN] @ W[DIN, DOUT]   (no bias here;
// the GCN layer's bias is applied after the adjacency aggregation)
// ---------------------------------------------------------------------------
template<int DIN, int DOUT>
__global__ void __launch_bounds__(256, 1)
dense_gemm(const float* __restrict__ H, const float* __restrict__ W,
           float* __restrict__ P)
{
    constexpr int TPR = DOUT / 4;       // threads per row (16 or 4)
    constexpr int RPB = 256 / TPR;      // rows per block (16 or 64)
    constexpr int HSTRIDE = DIN + 4;    // pad: keep 16B align + kill conflicts

    __shared__ __align__(16) float Ws[DIN * DOUT];
    __shared__ __align__(16) float Hs[RPB * HSTRIDE];

    const int tid = threadIdx.x;
    const int r0 = blockIdx.x * RPB;

    for (int i = tid; i < DIN * DOUT / 4; i += 256)
        reinterpret_cast<float4*>(Ws)[i] = reinterpret_cast<const float4*>(W)[i];

    for (int i = tid; i < RPB * DIN / 4; i += 256) {
        const int r = i / (DIN / 4);
        const int c = i % (DIN / 4);
        *reinterpret_cast<float4*>(&Hs[r * HSTRIDE + c * 4]) =
            *reinterpret_cast<const float4*>(&H[(size_t)(r0 + r) * DIN + c * 4]);
    }
    __syncthreads();

    const int lr = tid / TPR;
    const int lc = (tid % TPR) * 4;

    float4 accv = make_float4(0.f, 0.f, 0.f, 0.f);
    #pragma unroll
    for (int k = 0; k < DIN; k++) {
        const float h = Hs[lr * HSTRIDE + k];
        const float4 w = *reinterpret_cast<const float4*>(&Ws[k * DOUT + lc]);
        accv.x = fmaf(h, w.x, accv.x);
        accv.y = fmaf(h, w.y, accv.y);
        accv.z = fmaf(h, w.z, accv.z);
        accv.w = fmaf(h, w.w, accv.w);
    }
    *reinterpret_cast<float4*>(&P[(size_t)(r0 + lr) * DOUT + lc]) = accv;
}

// ---------------------------------------------------------------------------
// kernel_launch: 4 GCN layers, kernels only (graph-capturable, alloc-free)
// ---------------------------------------------------------------------------
extern "C" void kernel_launch(void* const* d_in, const int* in_sizes, int n_in,
                              void* d_out, int out_size)
{
    const float* x     = (const float*)d_in[0];   // [N, 128]
    const float* adj   = (const float*)d_in[1];   // [N, N]
    const float* W_in  = (const float*)d_in[2];   // [128, 64]
    const float* b_in  = (const float*)d_in[3];   // [64]
    const float* W_hid = (const float*)d_in[4];   // [2, 64, 64]
    const float* b_hid = (const float*)d_in[5];   // [2, 64]
    const float* W_out = (const float*)d_in[6];   // [64, 16]
    const float* b_out = (const float*)d_in[7];   // [16]
    float* out = (float*)d_out;                   // [N, 16]

    float *h_buf = nullptr, *p_buf = nullptr;
    cudaGetSymbolAddress((void**)&h_buf, g_h);
    cudaGetSymbolAddress((void**)&p_buf, g_p);

    const dim3 blk(256);

    // Layer 1: h = adj @ (x @ W_in) + b_in
    dense_gemm<128, 64><<<NROWS / 16, blk>>>(x, W_in, p_buf);
    gcn_aggregate<64><<<NROWS / 128, blk>>>(adj, p_buf, b_in, h_buf);

    // Hidden layer 0
    dense_gemm<64, 64><<<NROWS / 16, blk>>>(h_buf, W_hid, p_buf);
    gcn_aggregate<64><<<NROWS / 128, blk>>>(adj, p_buf, b_hid, h_buf);

    // Hidden layer 1
    dense_gemm<64, 64><<<NROWS / 16, blk>>>(h_buf, W_hid + 64 * 64, p_buf);
    gcn_aggregate<64><<<NROWS / 128, blk>>>(adj, p_buf, b_hid + 64, h_buf);

    // Output layer: out = adj @ (h @ W_out) + b_out
    dense_gemm<64, 16><<<NROWS / 64, blk>>>(h_buf, W_out, p_buf);
    gcn_aggregate<16><<<NROWS / 128, blk>>>(adj, p_buf, b_out, out);
}

// round 15
// speedup vs baseline: 1.0004x; 1.0004x over previous
#include <cuda_runtime.h>
#include <cstdint>
#include <cstddef>

#define NROWS 16384

// Scratch ping-pong buffers (allocation-free: __device__ globals).
__device__ float g_h[NROWS * 64];
__device__ float g_p[NROWS * 64];

// ---------------------------------------------------------------------------
// Packed f32x2 helpers (sm_103a FFMA2 — only reachable via PTX)
// ---------------------------------------------------------------------------
__device__ __forceinline__ unsigned long long bcast2(float x) {
    unsigned long long r;
    unsigned xi = __float_as_uint(x);
    asm("mov.b64 %0, {%1, %1};" : "=l"(r) : "r"(xi));
    return r;
}
__device__ __forceinline__ void fma2(unsigned long long& d,
                                     unsigned long long a,
                                     unsigned long long b) {
    asm("fma.rn.f32x2 %0, %1, %2, %0;" : "+l"(d) : "l"(a), "l"(b));
}
__device__ __forceinline__ void cp_async16(uint32_t dst, const void* src) {
    asm volatile("cp.async.cg.shared.global [%0], [%1], 16;" :: "r"(dst), "l"(src));
}
__device__ __forceinline__ void cp_commit() {
    asm volatile("cp.async.commit_group;" ::: "memory");
}
__device__ __forceinline__ void cp_wait_all() {
    asm volatile("cp.async.wait_group 0;" ::: "memory");
}

// ---------------------------------------------------------------------------
// Big aggregation: C[N, D] = A[N, N] @ P[N, D] + bias[D]
//   BM = 128 rows per block, BN = D (full width), BK = 32.
//   256 threads; per-thread tile: 8 rows (4 f32x2 pairs) x TN cols, TN = D/16.
//   A tile in smem transposed [k][m] with stride 130 (8B-aligned pair loads).
//   A is register double-buffered (LDG.128), P double-buffered via cp.async.
// ---------------------------------------------------------------------------
template<int D>
__global__ void __launch_bounds__(256, 1)
gcn_aggregate(const float* __restrict__ A, const float* __restrict__ P,
              const float* __restrict__ bias, float* __restrict__ C)
{
    constexpr int BM = 128;
    constexpr int BK = 32;
    constexpr int SAS = BM + 2;   // 130: 8B-aligned rows, <=2-way STS conflict
    constexpr int TN = D / 16;    // 4 (D=64) or 1 (D=16)
    constexpr int PF4 = BK * D / 4;  // float4 count of P tile

    __shared__ __align__(16) float As[BK * SAS];
    __shared__ __align__(16) float Ps[2][BK * D];

    const int tid = threadIdx.x;
    const int tx  = tid & 15;     // column group (16)
    const int ty  = tid >> 4;     // row group (16) -> rows ty*8 .. ty*8+7
    const int m0  = blockIdx.x * BM;
    const int lm  = tid >> 3;            // loader row base (0..31)
    const int lk4 = (tid & 7) << 2;      // loader k offset (0,4,..,28)

    const uint32_t ps_base0 = (uint32_t)__cvta_generic_to_shared(&Ps[0][0]);
    const uint32_t ps_base1 = (uint32_t)__cvta_generic_to_shared(&Ps[1][0]);

    unsigned long long acc[4][TN];
    #pragma unroll
    for (int mi = 0; mi < 4; mi++)
        #pragma unroll
        for (int n = 0; n < TN; n++)
            acc[mi][n] = 0ull;

    float4 a_reg[4];

    // ---- prologue: tile 0 ----
    for (int i = tid; i < PF4; i += 256) {
        const int k = i / (D / 4);
        const int c = i % (D / 4);
        cp_async16(ps_base0 + (uint32_t)((k * D + c * 4) * 4),
                   P + (size_t)k * D + c * 4);
    }
    cp_commit();

    #pragma unroll
    for (int j = 0; j < 4; j++)
        a_reg[j] = *reinterpret_cast<const float4*>(
            A + (size_t)(m0 + lm + j * 32) * NROWS + lk4);
    #pragma unroll
    for (int j = 0; j < 4; j++) {
        const int m = lm + j * 32;
        As[(lk4 + 0) * SAS + m] = a_reg[j].x;
        As[(lk4 + 1) * SAS + m] = a_reg[j].y;
        As[(lk4 + 2) * SAS + m] = a_reg[j].z;
        As[(lk4 + 3) * SAS + m] = a_reg[j].w;
    }
    cp_wait_all();
    __syncthreads();

    const int KT = NROWS / BK;   // 512
    for (int kt = 0; kt < KT; kt++) {
        const bool more = (kt + 1) < KT;
        const int k0n = (kt + 1) * BK;
        if (more) {
            // prefetch next A tile into registers
            #pragma unroll
            for (int j = 0; j < 4; j++)
                a_reg[j] = *reinterpret_cast<const float4*>(
                    A + (size_t)(m0 + lm + j * 32) * NROWS + k0n + lk4);
            // prefetch next P tile via cp.async into the other buffer
            const uint32_t pb = ((kt + 1) & 1) ? ps_base1 : ps_base0;
            for (int i = tid; i < PF4; i += 256) {
                const int k = i / (D / 4);
                const int c = i % (D / 4);
                cp_async16(pb + (uint32_t)((k * D + c * 4) * 4),
                           P + (size_t)(k0n + k) * D + c * 4);
            }
            cp_commit();
        }

        // ---- compute on current tile ----
        const float* ps = Ps[kt & 1];
        #pragma unroll
        for (int k = 0; k < BK; k++) {
            unsigned long long a2[4];
            #pragma unroll
            for (int mi = 0; mi < 4; mi++)
                a2[mi] = *reinterpret_cast<const unsigned long long*>(
                    &As[k * SAS + ty * 8 + mi * 2]);
            if constexpr (TN == 4) {
                const float4 pv = *reinterpret_cast<const float4*>(&ps[k * D + tx * 4]);
                const unsigned long long pb0 = bcast2(pv.x);
                const unsigned long long pb1 = bcast2(pv.y);
                const unsigned long long pb2 = bcast2(pv.z);
                const unsigned long long pb3 = bcast2(pv.w);
                #pragma unroll
                for (int mi = 0; mi < 4; mi++) {
                    fma2(acc[mi][0], a2[mi], pb0);
                    fma2(acc[mi][1], a2[mi], pb1);
                    fma2(acc[mi][2], a2[mi], pb2);
                    fma2(acc[mi][3], a2[mi], pb3);
                }
            } else {
                const unsigned long long pb0 = bcast2(ps[k * D + tx]);
                #pragma unroll
                for (int mi = 0; mi < 4; mi++)
                    fma2(acc[mi][0], a2[mi], pb0);
            }
        }
        __syncthreads();   // compute done, As free for overwrite

        if (more) {
            #pragma unroll
            for (int j = 0; j < 4; j++) {
                const int m = lm + j * 32;
                As[(lk4 + 0) * SAS + m] = a_reg[j].x;
                As[(lk4 + 1) * SAS + m] = a_reg[j].y;
                As[(lk4 + 2) * SAS + m] = a_reg[j].z;
                As[(lk4 + 3) * SAS + m] = a_reg[j].w;
            }
            cp_wait_all();
        }
        __syncthreads();   // As + Ps[next] ready
    }

    // ---- epilogue: add bias, store ----
    float bv[TN];
    #pragma unroll
    for (int n = 0; n < TN; n++) bv[n] = bias[tx * TN + n];

    #pragma unroll
    for (int mi = 0; mi < 4; mi++) {
        const int row = m0 + ty * 8 + mi * 2;
        #pragma unroll
        for (int n = 0; n < TN; n++) {
            const unsigned long long v = acc[mi][n];
            const float lo = __uint_as_float((unsigned)(v & 0xffffffffull));
            const float hi = __uint_as_float((unsigned)(v >> 32));
            C[(size_t)row * D + tx * TN + n]       = lo + bv[n];
            C[(size_t)(row + 1) * D + tx * TN + n] = hi + bv[n];
        }
    }
}

// ---------------------------------------------------------------------------
// Small dense GEMM: P[N, DOUT] = H[N, DIN] @ W[DIN, DOUT]   (no bias here;
// the GCN layer's bias is applied after the adjacency aggregation)
// ---------------------------------------------------------------------------
template<int DIN, int DOUT>
__global__ void __launch_bounds__(256, 1)
dense_gemm(const float* __restrict__ H, const float* __restrict__ W,
           float* __restrict__ P)
{
    constexpr int TPR = DOUT / 4;       // threads per row (16 or 4)
    constexpr int RPB = 256 / TPR;      // rows per block (16 or 64)
    constexpr int HSTRIDE = DIN + 4;    // pad: keep 16B align + kill conflicts

    __shared__ __align__(16) float Ws[DIN * DOUT];
    __shared__ __align__(16) float Hs[RPB * HSTRIDE];

    const int tid = threadIdx.x;
    const int r0 = blockIdx.x * RPB;

    for (int i = tid; i < DIN * DOUT / 4; i += 256)
        reinterpret_cast<float4*>(Ws)[i] = reinterpret_cast<const float4*>(W)[i];

    for (int i = tid; i < RPB * DIN / 4; i += 256) {
        const int r = i / (DIN / 4);
        const int c = i % (DIN / 4);
        *reinterpret_cast<float4*>(&Hs[r * HSTRIDE + c * 4]) =
            *reinterpret_cast<const float4*>(&H[(size_t)(r0 + r) * DIN + c * 4]);
    }
    __syncthreads();

    const int lr = tid / TPR;
    const int lc = (tid % TPR) * 4;

    float4 accv = make_float4(0.f, 0.f, 0.f, 0.f);
    #pragma unroll
    for (int k = 0; k < DIN; k++) {
        const float h = Hs[lr * HSTRIDE + k];
        const float4 w = *reinterpret_cast<const float4*>(&Ws[k * DOUT + lc]);
        accv.x = fmaf(h, w.x, accv.x);
        accv.y = fmaf(h, w.y, accv.y);
        accv.z = fmaf(h, w.z, accv.z);
        accv.w = fmaf(h, w.w, accv.w);
    }
    *reinterpret_cast<float4*>(&P[(size_t)(r0 + lr) * DOUT + lc]) = accv;
}

// ---------------------------------------------------------------------------
// kernel_launch: 4 GCN layers, kernels only (graph-capturable, alloc-free)
// ---------------------------------------------------------------------------
extern "C" void kernel_launch(void* const* d_in, const int* in_sizes, int n_in,
                              void* d_out, int out_size)
{
    const float* x     = (const float*)d_in[0];   // [N, 128]
    const float* adj   = (const float*)d_in[1];   // [N, N]
    const float* W_in  = (const float*)d_in[2];   // [128, 64]
    const float* b_in  = (const float*)d_in[3];   // [64]
    const float* W_hid = (const float*)d_in[4];   // [2, 64, 64]
    const float* b_hid = (const float*)d_in[5];   // [2, 64]
    const float* W_out = (const float*)d_in[6];   // [64, 16]
    const float* b_out = (const float*)d_in[7];   // [16]
    float* out = (float*)d_out;                   // [N, 16]

    float *h_buf = nullptr, *p_buf = nullptr;
    cudaGetSymbolAddress((void**)&h_buf, g_h);
    cudaGetSymbolAddress((void**)&p_buf, g_p);

    const dim3 blk(256);

    // Layer 1: h = adj @ (x @ W_in) + b_in
    dense_gemm<128, 64><<<NROWS / 16, blk>>>(x, W_in, p_buf);
    gcn_aggregate<64><<<NROWS / 128, blk>>>(adj, p_buf, b_in, h_buf);

    // Hidden layer 0
    dense_gemm<64, 64><<<NROWS / 16, blk>>>(h_buf, W_hid, p_buf);
    gcn_aggregate<64><<<NROWS / 128, blk>>>(adj, p_buf, b_hid, h_buf);

    // Hidden layer 1
    dense_gemm<64, 64><<<NROWS / 16, blk>>>(h_buf, W_hid + 64 * 64, p_buf);
    gcn_aggregate<64><<<NROWS / 128, blk>>>(adj, p_buf, b_hid + 64, h_buf);

    // Output layer: out = adj @ (h @ W_out) + b_out
    dense_gemm<64, 16><<<NROWS / 64, blk>>>(h_buf, W_out, p_buf);
    gcn_aggregate<16><<<NROWS / 128, blk>>>(adj, p_buf, b_out, out);
}

// round 16
// speedup vs baseline: 1.0006x; 1.0002x over previous
#include <cuda_runtime.h>
#include <cstdint>
#include <cstddef>

#define NROWS 16384

// Scratch ping-pong buffers (allocation-free: __device__ globals).
__device__ float g_h[NROWS * 64];
__device__ float g_p[NROWS * 64];

// ---------------------------------------------------------------------------
// Packed f32x2 helpers (sm_103a FFMA2 — only reachable via PTX)
// ---------------------------------------------------------------------------
__device__ __forceinline__ unsigned long long bcast2(float x) {
    unsigned long long r;
    unsigned xi = __float_as_uint(x);
    asm("mov.b64 %0, {%1, %1};" : "=l"(r) : "r"(xi));
    return r;
}
__device__ __forceinline__ void fma2(unsigned long long& d,
                                     unsigned long long a,
                                     unsigned long long b) {
    asm("fma.rn.f32x2 %0, %1, %2, %0;" : "+l"(d) : "l"(a), "l"(b));
}
__device__ __forceinline__ void cp_async16(uint32_t dst, const void* src) {
    asm volatile("cp.async.cg.shared.global [%0], [%1], 16;" :: "r"(dst), "l"(src));
}
__device__ __forceinline__ void cp_commit() {
    asm volatile("cp.async.commit_group;" ::: "memory");
}
__device__ __forceinline__ void cp_wait_all() {
    asm volatile("cp.async.wait_group 0;" ::: "memory");
}

// ---------------------------------------------------------------------------
// Big aggregation: C[N, D] = A[N, N] @ P[N, D] + bias[D]
//   BM = 128 rows per block, BN = D (full width), BK = 32.
//   256 threads; per-thread tile: 8 rows (4 f32x2 pairs) x TN cols, TN = D/16.
//   A tile in smem transposed [k][m] with stride 130 (8B-aligned pair loads).
//   A is register double-buffered (LDG.128), P double-buffered via cp.async.
// ---------------------------------------------------------------------------
template<int D>
__global__ void __launch_bounds__(256, 1)
gcn_aggregate(const float* __restrict__ A, const float* __restrict__ P,
              const float* __restrict__ bias, float* __restrict__ C)
{
    constexpr int BM = 128;
    constexpr int BK = 32;
    constexpr int SAS = BM + 2;   // 130: 8B-aligned rows, <=2-way STS conflict
    constexpr int TN = D / 16;    // 4 (D=64) or 1 (D=16)
    constexpr int PF4 = BK * D / 4;  // float4 count of P tile

    __shared__ __align__(16) float As[BK * SAS];
    __shared__ __align__(16) float Ps[2][BK * D];

    const int tid = threadIdx.x;
    const int tx  = tid & 15;     // column group (16)
    const int ty  = tid >> 4;     // row group (16) -> rows ty*8 .. ty*8+7
    const int m0  = blockIdx.x * BM;
    const int lm  = tid >> 3;            // loader row base (0..31)
    const int lk4 = (tid & 7) << 2;      // loader k offset (0,4,..,28)

    const uint32_t ps_base0 = (uint32_t)__cvta_generic_to_shared(&Ps[0][0]);
    const uint32_t ps_base1 = (uint32_t)__cvta_generic_to_shared(&Ps[1][0]);

    unsigned long long acc[4][TN];
    #pragma unroll
    for (int mi = 0; mi < 4; mi++)
        #pragma unroll
        for (int n = 0; n < TN; n++)
            acc[mi][n] = 0ull;

    float4 a_reg[4];

    // ---- prologue: tile 0 ----
    for (int i = tid; i < PF4; i += 256) {
        const int k = i / (D / 4);
        const int c = i % (D / 4);
        cp_async16(ps_base0 + (uint32_t)((k * D + c * 4) * 4),
                   P + (size_t)k * D + c * 4);
    }
    cp_commit();

    #pragma unroll
    for (int j = 0; j < 4; j++)
        a_reg[j] = *reinterpret_cast<const float4*>(
            A + (size_t)(m0 + lm + j * 32) * NROWS + lk4);
    #pragma unroll
    for (int j = 0; j < 4; j++) {
        const int m = lm + j * 32;
        As[(lk4 + 0) * SAS + m] = a_reg[j].x;
        As[(lk4 + 1) * SAS + m] = a_reg[j].y;
        As[(lk4 + 2) * SAS + m] = a_reg[j].z;
        As[(lk4 + 3) * SAS + m] = a_reg[j].w;
    }
    cp_wait_all();
    __syncthreads();

    const int KT = NROWS / BK;   // 512
    for (int kt = 0; kt < KT; kt++) {
        const bool more = (kt + 1) < KT;
        const int k0n = (kt + 1) * BK;
        if (more) {
            // prefetch next A tile into registers
            #pragma unroll
            for (int j = 0; j < 4; j++)
                a_reg[j] = *reinterpret_cast<const float4*>(
                    A + (size_t)(m0 + lm + j * 32) * NROWS + k0n + lk4);
            // prefetch next P tile via cp.async into the other buffer
            const uint32_t pb = ((kt + 1) & 1) ? ps_base1 : ps_base0;
            for (int i = tid; i < PF4; i += 256) {
                const int k = i / (D / 4);
                const int c = i % (D / 4);
                cp_async16(pb + (uint32_t)((k * D + c * 4) * 4),
                           P + (size_t)(k0n + k) * D + c * 4);
            }
            cp_commit();
        }

        // ---- compute on current tile ----
        const float* ps = Ps[kt & 1];
        #pragma unroll
        for (int k = 0; k < BK; k++) {
            unsigned long long a2[4];
            #pragma unroll
            for (int mi = 0; mi < 4; mi++)
                a2[mi] = *reinterpret_cast<const unsigned long long*>(
                    &As[k * SAS + ty * 8 + mi * 2]);
            if constexpr (TN == 4) {
                const float4 pv = *reinterpret_cast<const float4*>(&ps[k * D + tx * 4]);
                const unsigned long long pb0 = bcast2(pv.x);
                const unsigned long long pb1 = bcast2(pv.y);
                const unsigned long long pb2 = bcast2(pv.z);
                const unsigned long long pb3 = bcast2(pv.w);
                #pragma unroll
                for (int mi = 0; mi < 4; mi++) {
                    fma2(acc[mi][0], a2[mi], pb0);
                    fma2(acc[mi][1], a2[mi], pb1);
                    fma2(acc[mi][2], a2[mi], pb2);
                    fma2(acc[mi][3], a2[mi], pb3);
                }
            } else {
                const unsigned long long pb0 = bcast2(ps[k * D + tx]);
                #pragma unroll
                for (int mi = 0; mi < 4; mi++)
                    fma2(acc[mi][0], a2[mi], pb0);
            }
        }
        __syncthreads();   // compute done, As free for overwrite

        if (more) {
            #pragma unroll
            for (int j = 0; j < 4; j++) {
                const int m = lm + j * 32;
                As[(lk4 + 0) * SAS + m] = a_reg[j].x;
                As[(lk4 + 1) * SAS + m] = a_reg[j].y;
                As[(lk4 + 2) * SAS + m] = a_reg[j].z;
                As[(lk4 + 3) * SAS + m] = a_reg[j].w;
            }
            cp_wait_all();
        }
        __syncthreads();   // As + Ps[next] ready
    }

    // ---- epilogue: add bias, store ----
    float bv[TN];
    #pragma unroll
    for (int n = 0; n < TN; n++) bv[n] = bias[tx * TN + n];

    #pragma unroll
    for (int mi = 0; mi < 4; mi++) {
        const int row = m0 + ty * 8 + mi * 2;
        #pragma unroll
        for (int n = 0; n < TN; n++) {
            const unsigned long long v = acc[mi][n];
            const float lo = __uint_as_float((unsigned)(v & 0xffffffffull));
            const float hi = __uint_as_float((unsigned)(v >> 32));
            C[(size_t)row * D + tx * TN + n]       = lo + bv[n];
            C[(size_t)(row + 1) * D + tx * TN + n] = hi + bv[n];
        }
    }
}

// ---------------------------------------------------------------------------
// Small dense GEMM: P[N, DOUT] = H[N, DIN] @ W[DIN, DOUT]   (no bias here;
// the GCN layer's bias is applied after the adjacency aggregation)
// ---------------------------------------------------------------------------
template<int DIN, int DOUT>
__global__ void __launch_bounds__(256, 1)
dense_gemm(const float* __restrict__ H, const float* __restrict__ W,
           float* __restrict__ P)
{
    constexpr int TPR = DOUT / 4;       // threads per row (16 or 4)
    constexpr int RPB = 256 / TPR;      // rows per block (16 or 64)
    constexpr int HSTRIDE = DIN + 4;    // pad: keep 16B align + kill conflicts

    __shared__ __align__(16) float Ws[DIN * DOUT];
    __shared__ __align__(16) float Hs[RPB * HSTRIDE];

    const int tid = threadIdx.x;
    const int r0 = blockIdx.x * RPB;

    for (int i = tid; i < DIN * DOUT / 4; i += 256)
        reinterpret_cast<float4*>(Ws)[i] = reinterpret_cast<const float4*>(W)[i];

    for (int i = tid; i < RPB * DIN / 4; i += 256) {
        const int r = i / (DIN / 4);
        const int c = i % (DIN / 4);
        *reinterpret_cast<float4*>(&Hs[r * HSTRIDE + c * 4]) =
            *reinterpret_cast<const float4*>(&H[(size_t)(r0 + r) * DIN + c * 4]);
    }
    __syncthreads();

    const int lr = tid / TPR;
    const int lc = (tid % TPR) * 4;

    float4 accv = make_float4(0.f, 0.f, 0.f, 0.f);
    #pragma unroll
    for (int k = 0; k < DIN; k++) {
        const float h = Hs[lr * HSTRIDE + k];
        const float4 w = *reinterpret_cast<const float4*>(&Ws[k * DOUT + lc]);
        accv.x = fmaf(h, w.x, accv.x);
        accv.y = fmaf(h, w.y, accv.y);
        accv.z = fmaf(h, w.z, accv.z);
        accv.w = fmaf(h, w.w, accv.w);
    }
    *reinterpret_cast<float4*>(&P[(size_t)(r0 + lr) * DOUT + lc]) = accv;
}

// ---------------------------------------------------------------------------
// kernel_launch: 4 GCN layers, kernels only (graph-capturable, alloc-free)
// ---------------------------------------------------------------------------
extern "C" void kernel_launch(void* const* d_in, const int* in_sizes, int n_in,
                              void* d_out, int out_size)
{
    const float* x     = (const float*)d_in[0];   // [N, 128]
    const float* adj   = (const float*)d_in[1];   // [N, N]
    const float* W_in  = (const float*)d_in[2];   // [128, 64]
    const float* b_in  = (const float*)d_in[3];   // [64]
    const float* W_hid = (const float*)d_in[4];   // [2, 64, 64]
    const float* b_hid = (const float*)d_in[5];   // [2, 64]
    const float* W_out = (const float*)d_in[6];   // [64, 16]
    const float* b_out = (const float*)d_in[7];   // [16]
    float* out = (float*)d_out;                   // [N, 16]

    float *h_buf = nullptr, *p_buf = nullptr;
    cudaGetSymbolAddress((void**)&h_buf, g_h);
    cudaGetSymbolAddress((void**)&p_buf, g_p);

    const dim3 blk(256);

    // Layer 1: h = adj @ (x @ W_in) + b_in
    dense_gemm<128, 64><<<NROWS / 16, blk>>>(x, W_in, p_buf);
    gcn_aggregate<64><<<NROWS / 128, blk>>>(adj, p_buf, b_in, h_buf);

    // Hidden layer 0
    dense_gemm<64, 64><<<NROWS / 16, blk>>>(h_buf, W_hid, p_buf);
    gcn_aggregate<64><<<NROWS / 128, blk>>>(adj, p_buf, b_hid, h_buf);

    // Hidden layer 1
    dense_gemm<64, 64><<<NROWS / 16, blk>>>(h_buf, W_hid + 64 * 64, p_buf);
    gcn_aggregate<64><<<NROWS / 128, blk>>>(adj, p_buf, b_hid + 64, h_buf);

    // Output layer: out = adj @ (h @ W_out) + b_out
    dense_gemm<64, 16><<<NROWS / 64, blk>>>(h_buf, W_out, p_buf);
    gcn_aggregate<16><<<NROWS / 128, blk>>>(adj, p_buf, b_out, out);
}